// round 16
// baseline (speedup 1.0000x reference)
#include <cuda_runtime.h>
#include <math.h>

// Problem constants (fixed by setup_inputs)
#define BB 2
#define NN 16384
#define MQ 4096
#define C1 128
#define C2 256
#define FC 384          // feature channels (128 + 256)
#define VC 387          // 3 coords + 384 features (logical per-query channels)
#define GC 1024         // global feature channels
#define CT 1411         // total channels
#define VCOLS 1124      // output columns whose window touches per-query channels
#define GCOLS (MQ - VCOLS)   // 2972 columns depending only on global feats

// spatial grid for exact kNN
#define GS 32
#define CELLS (GS * GS * GS)
#define GH 0.25f
#define GXMIN (-4.0f)
#define GINVH 4.0f

#define FULL 0xffffffffu
#define SROWS 16        // output rows per segment-B block

// mega-kernel block ranges: [query kNN | segB | transpose]
#define QKB  (BB * (MQ / 8))                         // 1024 query blocks (8 q/blk)
#define SEGB (BB * (MQ / SROWS))                     // 512 segment-B blocks
#define TRN  (NN / 32)                               // 512 transpose n-tiles
#define TRC  (FC / 32)                               // 12 transpose c-tiles
#define TRB  (TRN * TRC * BB)                        // 12288 transpose blocks

// ---------------- scratch (static device memory; no allocations) -------------
__device__ float  g_w [BB * MQ * 3];       // normalized Gaussian weights
__device__ int    g_i [BB * MQ * 3];       // final kNN indices
__device__ float  g_ft[(long)BB * NN * FC];// transposed features [b][n][c]
__device__ int    g_cnt [BB * CELLS];      // per-cell point counts
__device__ int    g_cur [BB * CELLS];      // scatter cursors
__device__ int    g_strt[BB * (CELLS + 1)];// exclusive prefix (cell starts)
__device__ float4 g_bin [BB * NN];         // binned points (x,y,z, idx-bits)

__device__ __forceinline__ int cell_of(float x, float y, float z) {
    int cx = (int)floorf((x - GXMIN) * GINVH);
    int cy = (int)floorf((y - GXMIN) * GINVH);
    int cz = (int)floorf((z - GXMIN) * GINVH);
    cx = min(GS - 1, max(0, cx));
    cy = min(GS - 1, max(0, cy));
    cz = min(GS - 1, max(0, cz));
    return (cz * GS + cy) * GS + cx;
}

// ---------------- kernel 0: zero histogram -----------------------------------
__global__ void __launch_bounds__(256) zero_kernel() {
    int t = blockIdx.x * 256 + threadIdx.x;
    if (t < BB * CELLS) g_cnt[t] = 0;
}

// ---------------- kernel 1: histogram ----------------------------------------
__global__ void __launch_bounds__(256) hist_kernel(const float* __restrict__ P) {
    int t = blockIdx.x * 256 + threadIdx.x;     // 0 .. BB*NN-1
    int b = t / NN, n = t % NN;
    const float* Pb = P + b * 3 * NN;
    atomicAdd(&g_cnt[b * CELLS + cell_of(Pb[n], Pb[NN + n], Pb[2 * NN + n])], 1);
}

// ---------------- kernel 2: exclusive scan (one block per batch) -------------
__global__ void __launch_bounds__(1024) scan_kernel() {
    __shared__ int sums[1024];
    int b   = blockIdx.x;
    int tid = threadIdx.x;
    int base = tid * 32;
    int cnt[32], s = 0;
#pragma unroll
    for (int j = 0; j < 32; j++) { cnt[j] = g_cnt[b * CELLS + base + j]; s += cnt[j]; }
    sums[tid] = s;
    __syncthreads();
    for (int off = 1; off < 1024; off <<= 1) {
        int v = (tid >= off) ? sums[tid - off] : 0;
        __syncthreads();
        sums[tid] += v;
        __syncthreads();
    }
    int o = (tid == 0) ? 0 : sums[tid - 1];
#pragma unroll
    for (int j = 0; j < 32; j++) {
        g_strt[b * (CELLS + 1) + base + j] = o;
        g_cur [b * CELLS + base + j] = o;
        o += cnt[j];
    }
    if (tid == 1023) g_strt[b * (CELLS + 1) + CELLS] = o;   // == NN
}

// ---------------- kernel 3: scatter points into bins --------------------------
__global__ void __launch_bounds__(256) scatter_kernel(const float* __restrict__ P) {
    int t = blockIdx.x * 256 + threadIdx.x;     // 0 .. BB*NN-1
    int b = t / NN, n = t % NN;
    const float* Pb = P + b * 3 * NN;
    float x = Pb[n], y = Pb[NN + n], z = Pb[2 * NN + n];
    int c = cell_of(x, y, z);
    int slot = atomicAdd(&g_cur[b * CELLS + c], 1);
    g_bin[(long)b * NN + slot] = make_float4(x, y, z, __int_as_float(n));
}

// ---------------- kernel A: mega (query kNN | segB | transpose) ---------------
union SmemU {
    float t32[32][33];           // transpose tile
    float grow[GCOLS];           // segment-B pooled global row
};

__global__ void __launch_bounds__(256)
mega_kernel(const float* __restrict__ Q,
            const float* __restrict__ F1, const float* __restrict__ F2,
            const float* __restrict__ G,  float* __restrict__ out) {
    __shared__ SmemU su;

    // ======================= path 1: grid kNN (1 query per warp) ============
    if (blockIdx.x < QKB) {
        int wid  = threadIdx.x >> 5;
        int lane = threadIdx.x & 31;
        int q    = blockIdx.x * 8 + wid;        // 0 .. BB*MQ-1
        int b    = q / MQ, m = q % MQ;

        float qx = Q[b * 3 * MQ + m];
        float qy = Q[b * 3 * MQ + MQ + m];
        float qz = Q[b * 3 * MQ + 2 * MQ + m];

        int cx = min(GS - 1, max(0, (int)floorf((qx - GXMIN) * GINVH)));
        int cy = min(GS - 1, max(0, (int)floorf((qy - GXMIN) * GINVH)));
        int cz = min(GS - 1, max(0, (int)floorf((qz - GXMIN) * GINVH)));

        const int*    cs  = g_strt + b * (CELLS + 1);
        const float4* bin = g_bin  + (long)b * NN;

        unsigned long long lk0 = ~0ull, lk1 = ~0ull, lk2 = ~0ull;

        auto spanf = [&](int c0, int ncells) {
            int s = cs[c0];
            int e = cs[c0 + ncells];
            for (int j = s + lane; j < e; j += 32) {
                float4 p = bin[j];
                float dx = qx - p.x, dy = qy - p.y, dz = qz - p.z;
                float d2 = fmaf(dz, dz, fmaf(dy, dy, dx * dx));
                unsigned long long key =
                    ((unsigned long long)__float_as_uint(d2) << 32) |
                    (unsigned)__float_as_int(p.w);
                if (key < lk2) {
                    if (key < lk1) {
                        lk2 = lk1;
                        if (key < lk0) { lk1 = lk0; lk0 = key; }
                        else           { lk1 = key; }
                    } else lk2 = key;
                }
            }
        };
#define CELLI(X, Y, Z) (((Z) * GS + (Y)) * GS + (X))

        int R = 1;
        {   // initial 3x3x3 box
            int x0 = max(cx - 1, 0), x1 = min(cx + 1, GS - 1);
            for (int zz = max(cz - 1, 0); zz <= min(cz + 1, GS - 1); zz++)
                for (int yy = max(cy - 1, 0); yy <= min(cy + 1, GS - 1); yy++)
                    spanf(CELLI(x0, yy, zz), x1 - x0 + 1);
        }

        unsigned long long r0 = ~0ull, r1 = ~0ull, r2 = ~0ull;
        while (true) {
            // warp merge of lane-local top-3s (keys unique: idx in low bits)
            unsigned long long cur = lk0;
            int ptr = 0;
            for (int s3 = 0; s3 < 3; s3++) {
                unsigned long long mk = cur;
#pragma unroll
                for (int off = 16; off; off >>= 1) {
                    unsigned long long o = __shfl_xor_sync(FULL, mk, off);
                    if (o < mk) mk = o;
                }
                if (cur == mk) { ptr++; cur = (ptr == 1) ? lk1 : ((ptr == 2) ? lk2 : ~0ull); }
                if (s3 == 0) r0 = mk; else if (s3 == 1) r1 = mk; else r2 = mk;
            }
            int x0 = max(cx - R, 0), x1 = min(cx + R, GS - 1);
            int y0 = max(cy - R, 0), y1 = min(cy + R, GS - 1);
            int z0 = max(cz - R, 0), z1 = min(cz + R, GS - 1);
            bool fullcov = (x0 == 0) && (x1 == GS - 1) && (y0 == 0) &&
                           (y1 == GS - 1) && (z0 == 0) && (z1 == GS - 1);
            if (fullcov) break;
            if ((unsigned)(r2 >> 32) != 0xFFFFFFFFu) {
                float d3 = __uint_as_float((unsigned)(r2 >> 32));
                const float BIG = 1e30f;
                float fx = fminf((x0 == 0) ? BIG : (qx - (x0 * GH + GXMIN)),
                                 (x1 == GS - 1) ? BIG : ((x1 + 1) * GH + GXMIN - qx));
                float fy = fminf((y0 == 0) ? BIG : (qy - (y0 * GH + GXMIN)),
                                 (y1 == GS - 1) ? BIG : ((y1 + 1) * GH + GXMIN - qy));
                float fz = fminf((z0 == 0) ? BIG : (qz - (z0 * GH + GXMIN)),
                                 (z1 == GS - 1) ? BIG : ((z1 + 1) * GH + GXMIN - qz));
                float safe = fminf(fx, fminf(fy, fz));
                if (d3 < safe * safe) break;
            }
            R++;   // process shell Chebyshev == R (clamped)
            int nx0 = max(cx - R, 0), nx1 = min(cx + R, GS - 1);
            for (int zz = max(cz - R, 0); zz <= min(cz + R, GS - 1); zz++)
                for (int yy = max(cy - R, 0); yy <= min(cy + R, GS - 1); yy++) {
                    bool edge = (zz == cz - R) || (zz == cz + R) ||
                                (yy == cy - R) || (yy == cy + R);
                    if (edge) spanf(CELLI(nx0, yy, zz), nx1 - nx0 + 1);
                    else {
                        if (cx - R >= 0)      spanf(CELLI(cx - R, yy, zz), 1);
                        if (cx + R <= GS - 1) spanf(CELLI(cx + R, yy, zz), 1);
                    }
                }
        }
#undef CELLI

        if (lane == 0) {
            float d0  = __uint_as_float((unsigned)(r0 >> 32));
            float d1  = __uint_as_float((unsigned)(r1 >> 32));
            float d2v = __uint_as_float((unsigned)(r2 >> 32));
            int t = b * MQ + m;
            float e1 = expf(-0.5f * (d1  - d0));
            float e2 = expf(-0.5f * (d2v - d0));
            float inv = 1.0f / (1.0f + e1 + e2);
            g_w[t * 3]     = inv;
            g_w[t * 3 + 1] = e1 * inv;
            g_w[t * 3 + 2] = e2 * inv;
            g_i[t * 3]     = (int)(r0 & 0xFFFFFFFFu);
            g_i[t * 3 + 1] = (int)(r1 & 0xFFFFFFFFu);
            g_i[t * 3 + 2] = (int)(r2 & 0xFFFFFFFFu);
        }
        return;
    }

    // ======================= path 2: output segment B (global-only cols) ====
    if (blockIdx.x < QKB + SEGB) {
        int t  = blockIdx.x - QKB;
        int b  = t / (MQ / SROWS);
        int m0 = (t % (MQ / SROWS)) * SROWS;
        const float* Gb = G + b * GC;

        for (int j = threadIdx.x; j < GCOLS; j += 256) {
            int i  = VCOLS + j;
            int st = (i * CT) >> 12;
            int en = ((i + 1) * CT + 4095) >> 12;
            float a = __ldg(&Gb[st - VC]);
            if (en - st == 2) a = fmaxf(a, __ldg(&Gb[st + 1 - VC]));
            su.grow[j] = a;
        }
        __syncthreads();

        const float4* gr4 = (const float4*)su.grow;
#pragma unroll 2
        for (int r = 0; r < SROWS; r++) {
            float4* od = (float4*)(out + ((long)(b * MQ + m0 + r)) * MQ + VCOLS);
            for (int qq = threadIdx.x; qq < GCOLS / 4; qq += 256)
                __stcs(od + qq, gr4[qq]);
        }
        return;
    }

    // ======================= path 3: feature transpose ======================
    {
        int t  = blockIdx.x - QKB - SEGB;
        int n0 = (t % TRN) * 32;
        int cb = (t / TRN) % TRC;
        int b  = t / (TRN * TRC);
        const float* F;
        int C, c0, coff;
        if (cb < C1 / 32) { F = F1; C = C1; c0 = cb * 32;             coff = 0;  }
        else              { F = F2; C = C2; c0 = (cb - C1 / 32) * 32; coff = C1; }
        int tx = threadIdx.x & 31;
        int ty = threadIdx.x >> 5;

#pragma unroll
        for (int r = ty; r < 32; r += 8)
            su.t32[r][tx] = F[((long)(b * C + c0 + r)) * NN + n0 + tx];
        __syncthreads();
#pragma unroll
        for (int r = ty; r < 32; r += 8) {
            int n = n0 + r, c = c0 + tx;
            g_ft[((long)(b * NN + n)) * FC + coff + c] = su.t32[tx][r];
        }
    }
}

// ---------------- kernel B: fused interp + pool, segment A only -------------
#define RPB 8
__global__ void __launch_bounds__(256) pool_kernel(const float* __restrict__ Q,
                                                   const float* __restrict__ G,
                                                   float* __restrict__ out) {
    __shared__ float sv[RPB][VC + 1];   // [0..2]=coords, [3..386]=feat, [VC]=sg0
    __shared__ unsigned meta[VCOLS];    // st | (st2 << 16), branchless dual-max
    __shared__ float sw[RPB][3];
    __shared__ int   si[RPB][3];

    int blk = blockIdx.x;                 // 0 .. B*MQ/RPB - 1
    int b   = blk / (MQ / RPB);
    int m0  = (blk % (MQ / RPB)) * RPB;
    float sg0 = G[b * GC];                // only global channel reachable in i<VCOLS

    for (int i = threadIdx.x; i < VCOLS; i += 256) {
        unsigned st = (i * CT) >> 12;
        unsigned en = ((i + 1) * CT + 4095) >> 12;
        unsigned st2 = (en - st == 2) ? st + 1 : st;
        meta[i] = st | (st2 << 16);
    }
    if (threadIdx.x < RPB * 3) {
        int r = threadIdx.x / 3, k = threadIdx.x % 3;
        sw[r][k] = g_w[(b * MQ + m0 + r) * 3 + k];
        si[r][k] = g_i[(b * MQ + m0 + r) * 3 + k];
        sv[r][k] = Q[(b * 3 + k) * MQ + m0 + r];
    }
    if (threadIdx.x >= 32 && threadIdx.x < 32 + RPB)
        sv[threadIdx.x - 32][VC] = sg0;
    __syncthreads();

    for (int idx = threadIdx.x; idx < RPB * (FC / 4); idx += 256) {
        int r  = idx / (FC / 4);
        int c4 = idx % (FC / 4);
        float w0 = sw[r][0], w1 = sw[r][1], w2 = sw[r][2];
        const float4* f0 = (const float4*)(g_ft + ((long)(b * NN + si[r][0])) * FC);
        const float4* f1 = (const float4*)(g_ft + ((long)(b * NN + si[r][1])) * FC);
        const float4* f2 = (const float4*)(g_ft + ((long)(b * NN + si[r][2])) * FC);
        float4 a = f0[c4], bb = f1[c4], cc = f2[c4];
        float* dst = &sv[r][3 + c4 * 4];
        dst[0] = w0 * a.x + w1 * bb.x + w2 * cc.x;
        dst[1] = w0 * a.y + w1 * bb.y + w2 * cc.y;
        dst[2] = w0 * a.z + w1 * bb.z + w2 * cc.z;
        dst[3] = w0 * a.w + w1 * bb.w + w2 * cc.w;
    }
    __syncthreads();

#pragma unroll 2
    for (int r = 0; r < RPB; r++) {
        float* orow = out + ((long)(b * MQ + m0 + r)) * MQ;
        for (int qq = threadIdx.x; qq < VCOLS / 4; qq += 256) {
            float4 o;
            float* op = (float*)&o;
#pragma unroll
            for (int u = 0; u < 4; u++) {
                unsigned m = meta[qq * 4 + u];
                op[u] = fmaxf(sv[r][m & 0xffff], sv[r][m >> 16]);
            }
            __stcs(((float4*)orow) + qq, o);
        }
    }
}

// ---------------- launch -----------------------------------------------------
extern "C" void kernel_launch(void* const* d_in, const int* in_sizes, int n_in,
                              void* d_out, int out_size) {
    const float* P  = (const float*)d_in[0];   // original_pts [B,3,N]
    const float* Q  = (const float*)d_in[1];   // query_pts    [B,3,M]
    const float* F1 = (const float*)d_in[2];   // local_feat1  [B,128,N]
    const float* F2 = (const float*)d_in[3];   // local_feat2  [B,256,N]
    const float* G  = (const float*)d_in[4];   // global_feats [B,1024]
    float* out = (float*)d_out;                // [B,M,M]

    zero_kernel<<<(BB * CELLS + 255) / 256, 256>>>();
    hist_kernel<<<BB * NN / 256, 256>>>(P);
    scan_kernel<<<BB, 1024>>>();
    scatter_kernel<<<BB * NN / 256, 256>>>(P);
    mega_kernel<<<QKB + SEGB + TRB, 256>>>(Q, F1, F2, G, out);
    pool_kernel<<<BB * MQ / RPB, 256>>>(Q, G, out);
}

// round 17
// speedup vs baseline: 1.8857x; 1.8857x over previous
#include <cuda_runtime.h>
#include <math.h>

// Problem constants (fixed by setup_inputs)
#define BB 2
#define NN 16384
#define MQ 4096
#define C1 128
#define C2 256
#define FC 384          // feature channels (128 + 256)
#define VC 387          // 3 coords + 384 features (logical per-query channels)
#define GC 1024         // global feature channels
#define CT 1411         // total channels
#define VCOLS 1124      // output columns whose window touches per-query channels
#define GCOLS (MQ - VCOLS)   // 2972 columns depending only on global feats

#define TPTS 2048       // kNN smem tile points (32 KB of float4)
#define PPT (TPTS / 256)     // 8 points per thread per tile
#define KQW 2           // queries per warp (empirical optimum)
#define KWARPS 8        // warps per kNN block
#define KQB (KQW * KWARPS)   // 16 queries per block
#define FULL 0xffffffffu

#define SROWS 16        // output rows per segment-B block

// mega-kernel block ranges: [kNN | segB | transpose]
#define KNNB (BB * (MQ / KQB))                       // 512 kNN blocks
#define SEGB (BB * (MQ / SROWS))                     // 512 segment-B blocks
#define TRN  (NN / 32)                               // 512 transpose n-tiles
#define TRC  (FC / 32)                               // 12 transpose c-tiles
#define TRB  (TRN * TRC * BB)                        // 12288 transpose blocks

// ---------------- scratch (static device memory; no allocations) -------------
__device__ float  g_w [BB * MQ * 3];       // normalized Gaussian weights
__device__ int    g_i [BB * MQ * 3];       // final kNN indices
__device__ float  g_ft[(long)BB * NN * FC];// transposed features [b][n][c]

#define FINF __int_as_float(0x7f800000)

__device__ __forceinline__ void ins3(float t, int n,
                                     float& d0, float& d1, float& d2,
                                     int& i0, int& i1, int& i2) {
    if (t < d1) {
        d2 = d1; i2 = i1;
        if (t < d0) { d1 = d0; i1 = i0; d0 = t; i0 = n; }
        else        { d1 = t;  i1 = n; }
    } else { d2 = t; i2 = n; }
}

// ---------------- kernel A: mega (kNN | segB | transpose by block range) -----
union SmemU {
    float4 tile4[TPTS];          // kNN point tile (32 KB)
    float  t32[32][33];          // transpose tile
    float  grow[GCOLS];          // segment-B pooled global row (11.9 KB)
};

__global__ void __launch_bounds__(256)
mega_kernel(const float* __restrict__ P,  const float* __restrict__ Q,
            const float* __restrict__ F1, const float* __restrict__ F2,
            const float* __restrict__ G,  float* __restrict__ out) {
    __shared__ SmemU su;

    // ======================= path 1: kNN ===================================
    if (blockIdx.x < KNNB) {
        const int bpb = MQ / KQB;                 // 256 query-blocks per batch
        int b    = blockIdx.x / bpb;
        int q0   = (blockIdx.x % bpb) * KQB;
        int wid  = threadIdx.x >> 5;
        int lane = threadIdx.x & 31;

        float qx[KQW], qy[KQW], qz[KQW];
        int   mq[KQW];
#pragma unroll
        for (int g = 0; g < KQW; g++) {
            mq[g] = q0 + wid * KQW + g;
            qx[g] = Q[b * 3 * MQ + mq[g]];
            qy[g] = Q[b * 3 * MQ + MQ + mq[g]];
            qz[g] = Q[b * 3 * MQ + 2 * MQ + mq[g]];
        }

        float d0a[KQW], d1a[KQW], d2a[KQW];
        int   i0a[KQW], i1a[KQW], i2a[KQW];
#pragma unroll
        for (int g = 0; g < KQW; g++) {
            d0a[g] = FINF; d1a[g] = FINF; d2a[g] = FINF;
            i0a[g] = 0;    i1a[g] = 0;    i2a[g] = 0;
        }

        const float* Pb = P + b * 3 * NN;

        // prefetch tile 0 raw coordinates into registers
        float px[PPT], py[PPT], pz[PPT];
#pragma unroll
        for (int k = 0; k < PPT; k++) {
            int n = k * 256 + threadIdx.x;
            px[k] = Pb[n]; py[k] = Pb[NN + n]; pz[k] = Pb[2 * NN + n];
        }

        for (int tb = 0; tb < NN; tb += TPTS) {
            // store prefetched tile (preprocessed) to smem
#pragma unroll
            for (int k = 0; k < PPT; k++) {
                su.tile4[k * 256 + threadIdx.x] =
                    make_float4(-2.f * px[k], -2.f * py[k], -2.f * pz[k],
                                px[k] * px[k] + py[k] * py[k] + pz[k] * pz[k]);
            }
            __syncthreads();

            // prefetch NEXT tile raw coords (LDG latency hides under rounds)
            if (tb + TPTS < NN) {
#pragma unroll
                for (int k = 0; k < PPT; k++) {
                    int n = tb + TPTS + k * 256 + threadIdx.x;
                    px[k] = Pb[n]; py[k] = Pb[NN + n]; pz[k] = Pb[2 * NN + n];
                }
            }

            for (int r = 0; r < TPTS; r += 128) {      // 128 points per round
                float4 p0 = su.tile4[r + lane];
                float4 p1 = su.tile4[r + 32 + lane];
                float4 p2 = su.tile4[r + 64 + lane];
                float4 p3 = su.tile4[r + 96 + lane];
                float t0g[KQW], t1g[KQW], t2g[KQW], t3g[KQW], mng[KQW];
                bool hit = false;
#pragma unroll
                for (int g = 0; g < KQW; g++) {
                    float t0 = fmaf(qz[g], p0.z, fmaf(qy[g], p0.y, fmaf(qx[g], p0.x, p0.w)));
                    float t1 = fmaf(qz[g], p1.z, fmaf(qy[g], p1.y, fmaf(qx[g], p1.x, p1.w)));
                    float t2 = fmaf(qz[g], p2.z, fmaf(qy[g], p2.y, fmaf(qx[g], p2.x, p2.w)));
                    float t3 = fmaf(qz[g], p3.z, fmaf(qy[g], p3.y, fmaf(qx[g], p3.x, p3.w)));
                    t0g[g] = t0; t1g[g] = t1; t2g[g] = t2; t3g[g] = t3;
                    float mn = fminf(fminf(t0, t1), fminf(t2, t3));
                    mng[g] = mn;
                    hit |= (mn < d2a[g]);
                }
                if (__any_sync(FULL, hit)) {           // rare: top-3 update
#pragma unroll
                    for (int g = 0; g < KQW; g++) {
                        // one ballot per query; per hit lane broadcast 4 vals
                        unsigned bal = __ballot_sync(FULL, mng[g] < d2a[g]);
                        while (bal) {
                            int L = __ffs(bal) - 1; bal &= bal - 1;
                            float v0 = __shfl_sync(FULL, t0g[g], L);
                            float v1 = __shfl_sync(FULL, t1g[g], L);
                            float v2 = __shfl_sync(FULL, t2g[g], L);
                            float v3 = __shfl_sync(FULL, t3g[g], L);
                            int nb = tb + r + L;
                            if (v0 < d2a[g]) ins3(v0, nb,
                                d0a[g], d1a[g], d2a[g], i0a[g], i1a[g], i2a[g]);
                            if (v1 < d2a[g]) ins3(v1, nb + 32,
                                d0a[g], d1a[g], d2a[g], i0a[g], i1a[g], i2a[g]);
                            if (v2 < d2a[g]) ins3(v2, nb + 64,
                                d0a[g], d1a[g], d2a[g], i0a[g], i1a[g], i2a[g]);
                            if (v3 < d2a[g]) ins3(v3, nb + 96,
                                d0a[g], d1a[g], d2a[g], i0a[g], i1a[g], i2a[g]);
                        }
                    }
                }
            }
            __syncthreads();
        }

        if (lane == 0) {
#pragma unroll
            for (int g = 0; g < KQW; g++) {
                int t = b * MQ + mq[g];
                float e1 = expf(-0.5f * (d1a[g] - d0a[g]));
                float e2 = expf(-0.5f * (d2a[g] - d0a[g]));
                float inv = 1.0f / (1.0f + e1 + e2);
                g_w[t * 3]     = inv;
                g_w[t * 3 + 1] = e1 * inv;
                g_w[t * 3 + 2] = e2 * inv;
                g_i[t * 3]     = i0a[g];
                g_i[t * 3 + 1] = i1a[g];
                g_i[t * 3 + 2] = i2a[g];
            }
        }
        return;
    }

    // ======================= path 2: output segment B (global-only cols) ====
    if (blockIdx.x < KNNB + SEGB) {
        int t  = blockIdx.x - KNNB;
        int b  = t / (MQ / SROWS);
        int m0 = (t % (MQ / SROWS)) * SROWS;
        const float* Gb = G + b * GC;

        for (int j = threadIdx.x; j < GCOLS; j += 256) {
            int i  = VCOLS + j;
            int st = (i * CT) >> 12;
            int en = ((i + 1) * CT + 4095) >> 12;
            float a = __ldg(&Gb[st - VC]);
            if (en - st == 2) a = fmaxf(a, __ldg(&Gb[st + 1 - VC]));
            su.grow[j] = a;
        }
        __syncthreads();

        const float4* gr4 = (const float4*)su.grow;
#pragma unroll 2
        for (int r = 0; r < SROWS; r++) {
            float4* od = (float4*)(out + ((long)(b * MQ + m0 + r)) * MQ + VCOLS);
            for (int q = threadIdx.x; q < GCOLS / 4; q += 256)
                __stcs(od + q, gr4[q]);
        }
        return;
    }

    // ======================= path 3: feature transpose ======================
    {
        int t  = blockIdx.x - KNNB - SEGB;
        int n0 = (t % TRN) * 32;
        int cb = (t / TRN) % TRC;
        int b  = t / (TRN * TRC);
        const float* F;
        int C, c0, coff;
        if (cb < C1 / 32) { F = F1; C = C1; c0 = cb * 32;             coff = 0;  }
        else              { F = F2; C = C2; c0 = (cb - C1 / 32) * 32; coff = C1; }
        int tx = threadIdx.x & 31;
        int ty = threadIdx.x >> 5;

#pragma unroll
        for (int r = ty; r < 32; r += 8)
            su.t32[r][tx] = F[((long)(b * C + c0 + r)) * NN + n0 + tx];
        __syncthreads();
#pragma unroll
        for (int r = ty; r < 32; r += 8) {
            int n = n0 + r, c = c0 + tx;
            g_ft[((long)(b * NN + n)) * FC + coff + c] = su.t32[tx][r];
        }
    }
}

// ---------------- kernel B: fused interp + pool, segment A only -------------
#define RPB 8
__global__ void __launch_bounds__(256) pool_kernel(const float* __restrict__ Q,
                                                   const float* __restrict__ G,
                                                   float* __restrict__ out) {
    __shared__ float sv[RPB][VC + 1];   // [0..2]=coords, [3..386]=feat, [VC]=sg0
    __shared__ unsigned meta[VCOLS];    // st | (st2 << 16), branchless dual-max
    __shared__ float sw[RPB][3];
    __shared__ int   si[RPB][3];

    int blk = blockIdx.x;                 // 0 .. B*MQ/RPB - 1
    int b   = blk / (MQ / RPB);
    int m0  = (blk % (MQ / RPB)) * RPB;
    float sg0 = G[b * GC];                // only global channel reachable in i<VCOLS

    for (int i = threadIdx.x; i < VCOLS; i += 256) {
        unsigned st = (i * CT) >> 12;
        unsigned en = ((i + 1) * CT + 4095) >> 12;
        unsigned st2 = (en - st == 2) ? st + 1 : st;   // st2==VC handled via sv[.][VC]
        meta[i] = st | (st2 << 16);
    }
    if (threadIdx.x < RPB * 3) {
        int r = threadIdx.x / 3, k = threadIdx.x % 3;
        sw[r][k] = g_w[(b * MQ + m0 + r) * 3 + k];
        si[r][k] = g_i[(b * MQ + m0 + r) * 3 + k];
        sv[r][k] = Q[(b * 3 + k) * MQ + m0 + r];
    }
    if (threadIdx.x >= 32 && threadIdx.x < 32 + RPB)
        sv[threadIdx.x - 32][VC] = sg0;
    __syncthreads();

    // interpolation: RPB rows x 96 float4 tasks; gathers are contiguous 1536B rows
    for (int idx = threadIdx.x; idx < RPB * (FC / 4); idx += 256) {
        int r  = idx / (FC / 4);
        int c4 = idx % (FC / 4);
        float w0 = sw[r][0], w1 = sw[r][1], w2 = sw[r][2];
        const float4* f0 = (const float4*)(g_ft + ((long)(b * NN + si[r][0])) * FC);
        const float4* f1 = (const float4*)(g_ft + ((long)(b * NN + si[r][1])) * FC);
        const float4* f2 = (const float4*)(g_ft + ((long)(b * NN + si[r][2])) * FC);
        float4 a = f0[c4], bb = f1[c4], cc = f2[c4];
        float* dst = &sv[r][3 + c4 * 4];
        dst[0] = w0 * a.x + w1 * bb.x + w2 * cc.x;
        dst[1] = w0 * a.y + w1 * bb.y + w2 * cc.y;
        dst[2] = w0 * a.z + w1 * bb.z + w2 * cc.z;
        dst[3] = w0 * a.w + w1 * bb.w + w2 * cc.w;
    }
    __syncthreads();

#pragma unroll 2
    for (int r = 0; r < RPB; r++) {
        float* orow = out + ((long)(b * MQ + m0 + r)) * MQ;
        for (int q = threadIdx.x; q < VCOLS / 4; q += 256) {
            float4 o;
            float* op = (float*)&o;
#pragma unroll
            for (int u = 0; u < 4; u++) {
                unsigned m = meta[q * 4 + u];
                op[u] = fmaxf(sv[r][m & 0xffff], sv[r][m >> 16]);
            }
            __stcs(((float4*)orow) + q, o);
        }
    }
}

// ---------------- launch -----------------------------------------------------
extern "C" void kernel_launch(void* const* d_in, const int* in_sizes, int n_in,
                              void* d_out, int out_size) {
    const float* P  = (const float*)d_in[0];   // original_pts [B,3,N]
    const float* Q  = (const float*)d_in[1];   // query_pts    [B,3,M]
    const float* F1 = (const float*)d_in[2];   // local_feat1  [B,128,N]
    const float* F2 = (const float*)d_in[3];   // local_feat2  [B,256,N]
    const float* G  = (const float*)d_in[4];   // global_feats [B,1024]
    float* out = (float*)d_out;                // [B,M,M]

    mega_kernel<<<KNNB + SEGB + TRB, 256>>>(P, Q, F1, F2, G, out);
    pool_kernel<<<BB * MQ / RPB, 256>>>(Q, G, out);
}